// round 14
// baseline (speedup 1.0000x reference)
#include <cuda_runtime.h>
#include <cuda_fp16.h>
#include <cstdint>
#include <math.h>

// Problem constants
#define B_   16
#define CIN  64
#define COUT 64
#define H_   128
#define W_   128
#define HW   (H_*W_)          // 16384
#define NPIX (B_*COUT*HW)     // 16,777,216

#define XPAD 72               // halves per px row (144 B): ldmatrix rows 16B-aligned
#define WPAD 72
#define XROW (132 * XPAD)     // halves per staged input row

// ---------------- device scratch (static, no allocation) ----------------
__device__ __align__(16) __half g_wh[25 * 64 * WPAD];   // [khw][cout][WPAD]
__device__ float g_dog[25];
__device__ __align__(16) __half g_ybuf[NPIX];           // fp16 cosine-sim intermediate

__device__ __forceinline__ int refl(int i) {
    if (i < 0) return -i;
    if (i > 127) return 254 - i;
    return i;
}

__device__ __forceinline__ uint32_t smem_u32(const void* p) {
    uint32_t a;
    asm("{ .reg .u64 t; cvta.to.shared.u64 t, %1; cvt.u32.u64 %0, t; }"
        : "=r"(a) : "l"(p));
    return a;
}

// ---------------- kernel 1: weight prep (one block per (cout, tap)) ----------------
__global__ __launch_bounds__(64)
void prep_kernel(const float* __restrict__ w) {
    __shared__ float sh[2];
    const int tid = threadIdx.x;          // ci
    const int o   = blockIdx.x / 25;
    const int khw = blockIdx.x % 25;

    float v = w[o * 1600 + tid * 25 + khw];
    float s = v * v;
    #pragma unroll
    for (int off = 16; off > 0; off >>= 1)
        s += __shfl_down_sync(0xFFFFFFFFu, s, off);
    if ((tid & 31) == 0) sh[tid >> 5] = s;
    __syncthreads();
    float tot = sh[0] + sh[1];
    float inv = 1.f / fmaxf(sqrtf(tot), 1e-12f);
    g_wh[(size_t)(khw * 64 + o) * WPAD + tid] = __float2half(fabsf(v) * inv);

    if (blockIdx.x == 0 && tid < 25) {
        int u = tid / 5 - 2, vv = tid % 5 - 2;
        float d2 = (float)(u * u + vv * vv);
        const float two_pi = 6.2831853071795864769f;
        const float ae = 1.f / (two_pi * 1.44f);   // sigma_e = 1.2
        const float ai = 1.f / (two_pi * 1.96f);   // sigma_i = 1.4
        float val = ae * expf(-d2 / (2.f * 1.44f)) - ai * expf(-d2 / (2.f * 1.96f));
        g_dog[tid] = val / (ae - ai);
    }
}

// ---------------- kernel 2: fp16 HMMA conv + cosine, kw-split warp pairs ----------------
// Grid (64, 16): CTA = 2 output y-rows x 128 px x 64 cout. 512 thr = 16 warps.
// Tile t = warp&7: g = t>>2 (yrow), px0 = (t&3)*32. Warp pair (t, t+8) shares tile:
// warp<8 accumulates kw{0,1,2}, warp>=8 kw{3,4}; smem reduction in epilogue.
// smem: Ws[5kw][64][WPAD] 46080 | Xs[6 rows][132][XPAD] 114048 | Crow[6*132] | Ssum[2*132]
#define WS_BYTES (5 * 64 * WPAD * 2)            // 46080
#define XS_BYTES (6 * 132 * XPAD * 2)           // 114048
#define CROW_FLOATS (6 * 132)
#define SSUM_FLOATS (2 * 132)
#define DSMEM (WS_BYTES + XS_BYTES + (CROW_FLOATS + SSUM_FLOATS) * 4)  // 164352
// epilogue reuse of dead Ws/Xs region:
#define DUMP_OFF 0          // 8 tiles x 2048 floats = 65536 B
#define TBUF_OFF 65536      // 8 A-warps x 64*36 floats = 73728 B (ends 139264 < 160128)

__global__ __launch_bounds__(512, 1)
void main_mma_kernel(const float* __restrict__ x) {
    extern __shared__ char dsm[];
    __half* Ws   = (__half*)dsm;
    __half* Xs   = (__half*)(dsm + WS_BYTES);
    float*  Crow = (float*)(dsm + WS_BYTES + XS_BYTES);
    float*  Ssum = Crow + CROW_FLOATS;

    const int tid  = threadIdx.x;
    const int warp = tid >> 5;
    const int lane = tid & 31;
    const int t    = warp & 7;            // tile 0..7
    const int g    = t >> 2;              // output yrow 0..1
    const int px0  = (t & 3) * 32;        // pixel block
    const bool isA = warp < 8;            // kw {0,1,2} vs {3,4}
    const int b    = blockIdx.y;
    const int y0   = blockIdx.x * 2;

    // ---- stage X once: 6 input rows, transpose [ci][px] -> [px][ci] ----
    for (int task = warp; task < 96; task += 16) {
        int s = task >> 4, q = task & 15;
        int gy = refl(y0 + s - 2);
        const float* base = x + ((size_t)b * CIN + q * 4) * HW + (size_t)gy * W_;
        #pragma unroll
        for (int k = 0; k < 5; k++) {
            int c = lane + 32 * k;
            if (c < 132) {
                int gc = refl(c - 2);
                float v0 = base[0 * HW + gc];
                float v1 = base[1 * HW + gc];
                float v2 = base[2 * HW + gc];
                float v3 = base[3 * HW + gc];
                uint32_t p0, p1;
                asm("cvt.rn.f16x2.f32 %0, %1, %2;" : "=r"(p0) : "f"(v1), "f"(v0));
                asm("cvt.rn.f16x2.f32 %0, %1, %2;" : "=r"(p1) : "f"(v3), "f"(v2));
                *(uint2*)(Xs + (size_t)s * XROW + (size_t)c * XPAD + q * 4) =
                    make_uint2(p0, p1);
            }
        }
    }
    __syncthreads();

    // ---- per staged-row column sums of x^2 ----
    for (int tt = tid; tt < 792; tt += 512) {
        int s = tt / 132, c = tt - s * 132;
        const uint4* p = (const uint4*)(Xs + (size_t)s * XROW + (size_t)c * XPAD);
        float sacc = 0.f;
        #pragma unroll
        for (int i = 0; i < 8; i++) {
            uint4 u = p[i];
            const uint32_t uu[4] = {u.x, u.y, u.z, u.w};
            #pragma unroll
            for (int j = 0; j < 4; j++) {
                float2 f = __half22float2(*(const __half2*)&uu[j]);
                sacc = fmaf(f.x, f.x, fmaf(f.y, f.y, sacc));
            }
        }
        Crow[tt] = sacc;
    }
    __syncthreads();

    // ---- 5-row window sums -> Ssum[out row][padded col] ----
    for (int tt = tid; tt < 264; tt += 512) {
        int r = tt / 132, c = tt - r * 132;
        Ssum[tt] = Crow[(r + 0) * 132 + c] + Crow[(r + 1) * 132 + c]
                 + Crow[(r + 2) * 132 + c] + Crow[(r + 3) * 132 + c]
                 + Crow[(r + 4) * 132 + c];
    }

    // ---- accumulators ----
    float acc[2][8][4];
    #pragma unroll
    for (int mt = 0; mt < 2; mt++)
        #pragma unroll
        for (int nt = 0; nt < 8; nt++)
            #pragma unroll
            for (int i = 0; i < 4; i++) acc[mt][nt][i] = 0.f;

    // ldmatrix lane mappings (verified R5/R6)
    const int m_off = ((lane >> 3) & 1) * 8 + (lane & 7);      // A rows
    const int k_off = (lane >> 4) * 8;                          // A k segment
    const int brow  = (lane & 7) + ((lane >> 4) << 3);          // B n row
    const int bk    = ((lane >> 3) & 1) * 8;                    // B k segment

    const int kwb = isA ? 0 : 3;
    const int kwe = isA ? 3 : 5;

    for (int kh = 0; kh < 5; kh++) {
        __syncthreads();   // previous kh's taps done reading Ws
        {
            const uint4* src = (const uint4*)(g_wh + (size_t)kh * 5 * 64 * WPAD);
            uint4* dst = (uint4*)Ws;
            for (int i = tid; i < 2880; i += 512) dst[i] = src[i];
        }
        __syncthreads();

        for (int kw = kwb; kw < kwe; kw++) {
            const __half* Ab = Xs + (size_t)(g + kh) * XROW
                                  + (size_t)(px0 + kw) * XPAD;
            uint32_t a[4][2][4];
            #pragma unroll
            for (int kt = 0; kt < 4; kt++)
                #pragma unroll
                for (int mt = 0; mt < 2; mt++) {
                    uint32_t ad = smem_u32(Ab + (size_t)(mt * 16 + m_off) * XPAD
                                              + kt * 16 + k_off);
                    asm volatile(
                        "ldmatrix.sync.aligned.m8n8.x4.shared.b16 {%0,%1,%2,%3}, [%4];"
                        : "=r"(a[kt][mt][0]), "=r"(a[kt][mt][1]),
                          "=r"(a[kt][mt][2]), "=r"(a[kt][mt][3])
                        : "r"(ad));
                }
            #pragma unroll
            for (int np = 0; np < 4; np++) {
                #pragma unroll
                for (int kt = 0; kt < 4; kt++) {
                    uint32_t bb[4];
                    uint32_t bd = smem_u32(Ws + (size_t)(kw * 64 + np * 16 + brow) * WPAD
                                              + kt * 16 + bk);
                    asm volatile(
                        "ldmatrix.sync.aligned.m8n8.x4.shared.b16 {%0,%1,%2,%3}, [%4];"
                        : "=r"(bb[0]), "=r"(bb[1]), "=r"(bb[2]), "=r"(bb[3])
                        : "r"(bd));
                    #pragma unroll
                    for (int mt = 0; mt < 2; mt++) {
                        asm volatile(
                            "mma.sync.aligned.m16n8k16.row.col.f32.f16.f16.f32 "
                            "{%0,%1,%2,%3}, {%4,%5,%6,%7}, {%8,%9}, {%0,%1,%2,%3};"
                            : "+f"(acc[mt][2 * np][0]), "+f"(acc[mt][2 * np][1]),
                              "+f"(acc[mt][2 * np][2]), "+f"(acc[mt][2 * np][3])
                            : "r"(a[kt][mt][0]), "r"(a[kt][mt][1]),
                              "r"(a[kt][mt][2]), "r"(a[kt][mt][3]),
                              "r"(bb[0]), "r"(bb[1]));
                        asm volatile(
                            "mma.sync.aligned.m16n8k16.row.col.f32.f16.f16.f32 "
                            "{%0,%1,%2,%3}, {%4,%5,%6,%7}, {%8,%9}, {%0,%1,%2,%3};"
                            : "+f"(acc[mt][2 * np + 1][0]), "+f"(acc[mt][2 * np + 1][1]),
                              "+f"(acc[mt][2 * np + 1][2]), "+f"(acc[mt][2 * np + 1][3])
                            : "r"(a[kt][mt][0]), "r"(a[kt][mt][1]),
                              "r"(a[kt][mt][2]), "r"(a[kt][mt][3]),
                              "r"(bb[2]), "r"(bb[3]));
                    }
                }
            }
        }
    }
    __syncthreads();   // all taps done; Ws/Xs dead (Ssum at tail stays live)

    // ---- B-warps dump raw accumulators (numerators add before division) ----
    float* dump = (float*)(dsm + DUMP_OFF) + t * 2048;
    if (!isA) {
        int idx = 0;
        #pragma unroll
        for (int mt = 0; mt < 2; mt++)
            #pragma unroll
            for (int nt = 0; nt < 8; nt++)
                #pragma unroll
                for (int reg = 0; reg < 4; reg++)
                    dump[(idx++) * 32 + lane] = acc[mt][nt][reg];
    }
    __syncthreads();

    if (isA) {
        {
            int idx = 0;
            #pragma unroll
            for (int mt = 0; mt < 2; mt++)
                #pragma unroll
                for (int nt = 0; nt < 8; nt++)
                    #pragma unroll
                    for (int reg = 0; reg < 4; reg++)
                        acc[mt][nt][reg] += dump[(idx++) * 32 + lane];
        }

        // ---- cosine norm + smem transpose + coalesced fp16 store ----
        float inv[2][2];
        #pragma unroll
        for (int mt = 0; mt < 2; mt++)
            #pragma unroll
            for (int h = 0; h < 2; h++) {
                int p = px0 + mt * 16 + (lane >> 2) + h * 8;
                const float* sp = Ssum + g * 132 + p;
                float s = sp[0] + sp[1] + sp[2] + sp[3] + sp[4];
                inv[mt][h] = rsqrtf(s + 1e-8f);
            }

        float* buf = (float*)(dsm + TBUF_OFF) + warp * (64 * 36);
        #pragma unroll
        for (int mt = 0; mt < 2; mt++)
            #pragma unroll
            for (int nt = 0; nt < 8; nt++)
                #pragma unroll
                for (int reg = 0; reg < 4; reg++) {
                    int co  = nt * 8 + (lane & 3) * 2 + (reg & 1);
                    int pxl = mt * 16 + (lane >> 2) + (reg >> 1) * 8;
                    buf[co * 36 + pxl] = acc[mt][nt][reg] * inv[mt][reg >> 1];
                }
        __syncwarp();

        const int y = y0 + g;
        #pragma unroll
        for (int it = 0; it < 16; it++) {
            int row = it * 4 + (lane >> 3);   // cout
            int seg = lane & 7;               // 4-px segment
            float4 v = *(const float4*)&buf[row * 36 + seg * 4];
            uint32_t h01, h23;
            asm("cvt.rn.f16x2.f32 %0, %1, %2;" : "=r"(h01) : "f"(v.y), "f"(v.x));
            asm("cvt.rn.f16x2.f32 %0, %1, %2;" : "=r"(h23) : "f"(v.w), "f"(v.z));
            *(uint2*)&g_ybuf[(((size_t)b * COUT + row) * H_ + y) * W_ + px0 + seg * 4] =
                make_uint2(h01, h23);
        }
    }
}

// ---------------- kernel 3: depthwise 5x5 DoG (zero pad), fp16 input ----------------
__global__ __launch_bounds__(512)
void dog_kernel(float* __restrict__ out) {
    __shared__ float Ts[20 * 132];
    __shared__ float sd[25];

    const int tid = threadIdx.x;
    const int bc  = blockIdx.x;
    const int y0  = blockIdx.y * 16;

    if (tid < 25) sd[tid] = g_dog[tid];

    const __half* src = g_ybuf + (size_t)bc * HW;
    for (int idx = tid; idx < 20 * 66; idx += 512) {
        int rr = idx / 66;
        int c2 = (idx - rr * 66) * 2;
        int gy = y0 + rr - 2;
        float2 f = make_float2(0.f, 0.f);
        if (gy >= 0 && gy < H_) {
            int gx = c2 - 2;
            if (gx >= 0 && gx + 1 < W_) {
                f = __half22float2(*(const __half2*)(src + gy * W_ + gx));
            } else {
                if (gx >= 0 && gx < W_)         f.x = __half2float(src[gy * W_ + gx]);
                if (gx + 1 >= 0 && gx + 1 < W_) f.y = __half2float(src[gy * W_ + gx + 1]);
            }
        }
        Ts[rr * 132 + c2]     = f.x;
        Ts[rr * 132 + c2 + 1] = f.y;
    }
    __syncthreads();

    const int row = tid >> 5;
    const int t4  = (tid & 31) * 4;
    float a[4] = {0.f, 0.f, 0.f, 0.f};

    #pragma unroll
    for (int u = 0; u < 5; u++) {
        const float* rp = &Ts[(row + u) * 132 + t4];
        float4 xa = *(const float4*)rp;
        float4 xc = *(const float4*)(rp + 4);
        float xv[8] = {xa.x, xa.y, xa.z, xa.w, xc.x, xc.y, xc.z, xc.w};
        #pragma unroll
        for (int v = 0; v < 5; v++) {
            float dv = sd[u * 5 + v];
            #pragma unroll
            for (int j = 0; j < 4; j++) a[j] = fmaf(dv, xv[v + j], a[j]);
        }
    }
    float4 o = make_float4(a[0], a[1], a[2], a[3]);
    *(float4*)&out[(size_t)bc * HW + (y0 + row) * W_ + t4] = o;
}

// ---------------- launch ----------------
extern "C" void kernel_launch(void* const* d_in, const int* in_sizes, int n_in,
                              void* d_out, int out_size) {
    const float* x = (const float*)d_in[0];
    const float* w = (const float*)d_in[1];
    float* out = (float*)d_out;

    static bool attr_set = false;
    if (!attr_set) {
        cudaFuncSetAttribute(main_mma_kernel,
                             cudaFuncAttributeMaxDynamicSharedMemorySize, DSMEM);
        attr_set = true;
    }

    prep_kernel<<<1600, 64>>>(w);
    main_mma_kernel<<<dim3(64, 16), 512, DSMEM>>>(x);
    dog_kernel<<<dim3(1024, 8), 512>>>(out);
}

// round 15
// speedup vs baseline: 1.1186x; 1.1186x over previous
#include <cuda_runtime.h>
#include <cuda_fp16.h>
#include <cstdint>
#include <math.h>

// Problem constants
#define B_   16
#define CIN  64
#define COUT 64
#define H_   128
#define W_   128
#define HW   (H_*W_)          // 16384
#define NPIX (B_*COUT*HW)     // 16,777,216

#define XPAD 72               // halves per px row (144 B): ldmatrix rows 16B-aligned
#define WPAD 72
#define XROW (132 * XPAD)     // halves per staged input row

// ---------------- device scratch (static, no allocation) ----------------
__device__ __align__(16) __half g_wh[25 * 64 * WPAD];   // [khw][cout][WPAD]
__device__ float g_dog[25];
__device__ __align__(16) __half g_ybuf[NPIX];           // fp16 cosine-sim intermediate

__device__ __forceinline__ int refl(int i) {
    if (i < 0) return -i;
    if (i > 127) return 254 - i;
    return i;
}

__device__ __forceinline__ uint32_t smem_u32(const void* p) {
    uint32_t a;
    asm("{ .reg .u64 t; cvta.to.shared.u64 t, %1; cvt.u32.u64 %0, t; }"
        : "=r"(a) : "l"(p));
    return a;
}

// ---------------- kernel 1: weight prep ----------------
// grid 400, block 256: 64-thread slice s = tid>>6 handles one (cout, tap).
// One LDG -> shfl reduce -> 2-warp smem combine -> coalesced half store.
__global__ __launch_bounds__(256)
void prep_kernel(const float* __restrict__ w) {
    __shared__ float sh[4][2];
    const int tid = threadIdx.x;
    const int s   = tid >> 6;             // slice 0..3
    const int ci  = tid & 63;
    const int job = blockIdx.x * 4 + s;   // 0..1599
    const int o   = job / 25;
    const int khw = job % 25;

    float v = w[o * 1600 + ci * 25 + khw];
    float ss = v * v;
    #pragma unroll
    for (int off = 16; off > 0; off >>= 1)
        ss += __shfl_down_sync(0xFFFFFFFFu, ss, off);
    if ((ci & 31) == 0) sh[s][ci >> 5] = ss;
    __syncthreads();
    float tot = sh[s][0] + sh[s][1];
    float inv = 1.f / fmaxf(sqrtf(tot), 1e-12f);
    g_wh[(size_t)(khw * 64 + o) * WPAD + ci] = __float2half(fabsf(v) * inv);

    if (blockIdx.x == 0 && tid < 25) {
        int u = tid / 5 - 2, vv = tid % 5 - 2;
        float d2 = (float)(u * u + vv * vv);
        const float two_pi = 6.2831853071795864769f;
        const float ae = 1.f / (two_pi * 1.44f);   // sigma_e = 1.2
        const float ai = 1.f / (two_pi * 1.96f);   // sigma_i = 1.4
        float val = ae * expf(-d2 / (2.f * 1.44f)) - ai * expf(-d2 / (2.f * 1.96f));
        g_dog[tid] = val / (ae - ai);
    }
}

// ---------------- kernel 2: fp16 HMMA implicit-GEMM conv + cosine (R6 config) ----------------
// Grid (32, 16): CTA = 4 output y-rows x 128 px x 64 cout. 512 thr = 16 warps.
// Warp w: yrow g = w>>2, px block (w&3)*32. Warp tile M32 x N64. X staged ONCE (8 rows).
// smem: Ws[5kw][64][WPAD] 46080 | Xs[8 rows][132 px][XPAD] 152064 | Crow[8*132] | Ssum[4*132]
#define WS_BYTES (5 * 64 * WPAD * 2)            // 46080
#define XS_BYTES (8 * 132 * XPAD * 2)           // 152064
#define CROW_FLOATS (8 * 132)
#define SSUM_FLOATS (4 * 132)
#define DSMEM (WS_BYTES + XS_BYTES + (CROW_FLOATS + SSUM_FLOATS) * 4)  // 204480

__global__ __launch_bounds__(512, 1)
void main_mma_kernel(const float* __restrict__ x) {
    extern __shared__ char dsm[];
    __half* Ws   = (__half*)dsm;
    __half* Xs   = (__half*)(dsm + WS_BYTES);
    float*  Crow = (float*)(dsm + WS_BYTES + XS_BYTES);
    float*  Ssum = Crow + CROW_FLOATS;

    const int tid  = threadIdx.x;
    const int warp = tid >> 5;
    const int lane = tid & 31;
    const int g    = warp >> 2;           // output yrow 0..3
    const int px0  = (warp & 3) * 32;     // pixel block
    const int b    = blockIdx.y;
    const int y0   = blockIdx.x * 4;

    // ---- stage X once: 8 input rows, transpose [ci][px] -> [px][ci] ----
    for (int task = warp; task < 128; task += 16) {
        int s = task >> 4, q = task & 15;
        int gy = refl(y0 + s - 2);
        const float* base = x + ((size_t)b * CIN + q * 4) * HW + (size_t)gy * W_;
        #pragma unroll
        for (int k = 0; k < 5; k++) {
            int c = lane + 32 * k;
            if (c < 132) {
                int gc = refl(c - 2);
                float v0 = base[0 * HW + gc];
                float v1 = base[1 * HW + gc];
                float v2 = base[2 * HW + gc];
                float v3 = base[3 * HW + gc];
                uint32_t p0, p1;
                asm("cvt.rn.f16x2.f32 %0, %1, %2;" : "=r"(p0) : "f"(v1), "f"(v0));
                asm("cvt.rn.f16x2.f32 %0, %1, %2;" : "=r"(p1) : "f"(v3), "f"(v2));
                *(uint2*)(Xs + (size_t)s * XROW + (size_t)c * XPAD + q * 4) =
                    make_uint2(p0, p1);
            }
        }
    }
    __syncthreads();

    // ---- per staged-row column sums of x^2 ----
    for (int t = tid; t < 1056; t += 512) {
        int s = t / 132, c = t - s * 132;
        const uint4* p = (const uint4*)(Xs + (size_t)s * XROW + (size_t)c * XPAD);
        float sacc = 0.f;
        #pragma unroll
        for (int i = 0; i < 8; i++) {
            uint4 u = p[i];
            const uint32_t uu[4] = {u.x, u.y, u.z, u.w};
            #pragma unroll
            for (int j = 0; j < 4; j++) {
                float2 f = __half22float2(*(const __half2*)&uu[j]);
                sacc = fmaf(f.x, f.x, fmaf(f.y, f.y, sacc));
            }
        }
        Crow[t] = sacc;
    }
    __syncthreads();

    // ---- 5-row window sums -> Ssum[out row][padded col] ----
    for (int t = tid; t < 528; t += 512) {
        int r = t / 132, c = t - r * 132;
        Ssum[t] = Crow[(r + 0) * 132 + c] + Crow[(r + 1) * 132 + c]
                + Crow[(r + 2) * 132 + c] + Crow[(r + 3) * 132 + c]
                + Crow[(r + 4) * 132 + c];
    }

    // ---- accumulators ----
    float acc[2][8][4];
    #pragma unroll
    for (int mt = 0; mt < 2; mt++)
        #pragma unroll
        for (int nt = 0; nt < 8; nt++)
            #pragma unroll
            for (int i = 0; i < 4; i++) acc[mt][nt][i] = 0.f;

    // ldmatrix lane mappings (verified R5/R6)
    const int m_off = ((lane >> 3) & 1) * 8 + (lane & 7);      // A rows
    const int k_off = (lane >> 4) * 8;                          // A k segment
    const int brow  = (lane & 7) + ((lane >> 4) << 3);          // B n row
    const int bk    = ((lane >> 3) & 1) * 8;                    // B k segment

    for (int kh = 0; kh < 5; kh++) {
        __syncthreads();   // previous kh's taps done reading Ws
        {
            const uint4* src = (const uint4*)(g_wh + (size_t)kh * 5 * 64 * WPAD);
            uint4* dst = (uint4*)Ws;
            for (int i = tid; i < 2880; i += 512) dst[i] = src[i];
        }
        __syncthreads();

        #pragma unroll
        for (int kw = 0; kw < 5; kw++) {
            const __half* Ab = Xs + (size_t)(g + kh) * XROW
                                  + (size_t)(px0 + kw) * XPAD;
            // A fragments for all 4 k-chunks
            uint32_t a[4][2][4];
            #pragma unroll
            for (int kt = 0; kt < 4; kt++)
                #pragma unroll
                for (int mt = 0; mt < 2; mt++) {
                    uint32_t ad = smem_u32(Ab + (size_t)(mt * 16 + m_off) * XPAD
                                              + kt * 16 + k_off);
                    asm volatile(
                        "ldmatrix.sync.aligned.m8n8.x4.shared.b16 {%0,%1,%2,%3}, [%4];"
                        : "=r"(a[kt][mt][0]), "=r"(a[kt][mt][1]),
                          "=r"(a[kt][mt][2]), "=r"(a[kt][mt][3])
                        : "r"(ad));
                }
            // B via ldmatrix.x4: regs = {b0,b1 of nt even; b0,b1 of nt odd}
            #pragma unroll
            for (int np = 0; np < 4; np++) {
                #pragma unroll
                for (int kt = 0; kt < 4; kt++) {
                    uint32_t bb[4];
                    uint32_t bd = smem_u32(Ws + (size_t)(kw * 64 + np * 16 + brow) * WPAD
                                              + kt * 16 + bk);
                    asm volatile(
                        "ldmatrix.sync.aligned.m8n8.x4.shared.b16 {%0,%1,%2,%3}, [%4];"
                        : "=r"(bb[0]), "=r"(bb[1]), "=r"(bb[2]), "=r"(bb[3])
                        : "r"(bd));
                    #pragma unroll
                    for (int mt = 0; mt < 2; mt++) {
                        asm volatile(
                            "mma.sync.aligned.m16n8k16.row.col.f32.f16.f16.f32 "
                            "{%0,%1,%2,%3}, {%4,%5,%6,%7}, {%8,%9}, {%0,%1,%2,%3};"
                            : "+f"(acc[mt][2 * np][0]), "+f"(acc[mt][2 * np][1]),
                              "+f"(acc[mt][2 * np][2]), "+f"(acc[mt][2 * np][3])
                            : "r"(a[kt][mt][0]), "r"(a[kt][mt][1]),
                              "r"(a[kt][mt][2]), "r"(a[kt][mt][3]),
                              "r"(bb[0]), "r"(bb[1]));
                        asm volatile(
                            "mma.sync.aligned.m16n8k16.row.col.f32.f16.f16.f32 "
                            "{%0,%1,%2,%3}, {%4,%5,%6,%7}, {%8,%9}, {%0,%1,%2,%3};"
                            : "+f"(acc[mt][2 * np + 1][0]), "+f"(acc[mt][2 * np + 1][1]),
                              "+f"(acc[mt][2 * np + 1][2]), "+f"(acc[mt][2 * np + 1][3])
                            : "r"(a[kt][mt][0]), "r"(a[kt][mt][1]),
                              "r"(a[kt][mt][2]), "r"(a[kt][mt][3]),
                              "r"(bb[2]), "r"(bb[3]));
                    }
                }
            }
        }
    }
    __syncthreads();   // all taps done; Xs region reusable for epilogue

    // ---- epilogue: cosine norm + smem transpose + coalesced fp16 store ----
    float inv[2][2];
    #pragma unroll
    for (int mt = 0; mt < 2; mt++)
        #pragma unroll
        for (int h = 0; h < 2; h++) {
            int p = px0 + mt * 16 + (lane >> 2) + h * 8;
            const float* sp = Ssum + g * 132 + p;
            float s = sp[0] + sp[1] + sp[2] + sp[3] + sp[4];
            inv[mt][h] = rsqrtf(s + 1e-8f);
        }

    float* buf = (float*)(dsm + WS_BYTES) + warp * (64 * 36);
    #pragma unroll
    for (int mt = 0; mt < 2; mt++)
        #pragma unroll
        for (int nt = 0; nt < 8; nt++)
            #pragma unroll
            for (int reg = 0; reg < 4; reg++) {
                int co  = nt * 8 + (lane & 3) * 2 + (reg & 1);
                int pxl = mt * 16 + (lane >> 2) + (reg >> 1) * 8;
                buf[co * 36 + pxl] = acc[mt][nt][reg] * inv[mt][reg >> 1];
            }
    __syncwarp();

    const int y = y0 + g;
    #pragma unroll
    for (int it = 0; it < 16; it++) {
        int row = it * 4 + (lane >> 3);   // cout
        int seg = lane & 7;               // 4-px segment
        float4 v = *(const float4*)&buf[row * 36 + seg * 4];
        uint32_t h01, h23;
        asm("cvt.rn.f16x2.f32 %0, %1, %2;" : "=r"(h01) : "f"(v.y), "f"(v.x));
        asm("cvt.rn.f16x2.f32 %0, %1, %2;" : "=r"(h23) : "f"(v.w), "f"(v.z));
        *(uint2*)&g_ybuf[(((size_t)b * COUT + row) * H_ + y) * W_ + px0 + seg * 4] =
            make_uint2(h01, h23);
    }
}

// ---------------- kernel 3: depthwise 5x5 DoG (zero pad), fp16 input ----------------
__global__ __launch_bounds__(512)
void dog_kernel(float* __restrict__ out) {
    __shared__ float Ts[20 * 132];
    __shared__ float sd[25];

    const int tid = threadIdx.x;
    const int bc  = blockIdx.x;
    const int y0  = blockIdx.y * 16;

    if (tid < 25) sd[tid] = g_dog[tid];

    const __half* src = g_ybuf + (size_t)bc * HW;
    for (int idx = tid; idx < 20 * 66; idx += 512) {
        int rr = idx / 66;
        int c2 = (idx - rr * 66) * 2;         // padded col pair base
        int gy = y0 + rr - 2;
        float2 f = make_float2(0.f, 0.f);
        if (gy >= 0 && gy < H_) {
            int gx = c2 - 2;
            if (gx >= 0 && gx + 1 < W_) {
                f = __half22float2(*(const __half2*)(src + gy * W_ + gx));
            } else {
                if (gx >= 0 && gx < W_)         f.x = __half2float(src[gy * W_ + gx]);
                if (gx + 1 >= 0 && gx + 1 < W_) f.y = __half2float(src[gy * W_ + gx + 1]);
            }
        }
        Ts[rr * 132 + c2]     = f.x;
        Ts[rr * 132 + c2 + 1] = f.y;
    }
    __syncthreads();

    const int row = tid >> 5;
    const int t4  = (tid & 31) * 4;
    float a[4] = {0.f, 0.f, 0.f, 0.f};

    #pragma unroll
    for (int u = 0; u < 5; u++) {
        const float* rp = &Ts[(row + u) * 132 + t4];
        float4 xa = *(const float4*)rp;
        float4 xc = *(const float4*)(rp + 4);
        float xv[8] = {xa.x, xa.y, xa.z, xa.w, xc.x, xc.y, xc.z, xc.w};
        #pragma unroll
        for (int v = 0; v < 5; v++) {
            float dv = sd[u * 5 + v];
            #pragma unroll
            for (int j = 0; j < 4; j++) a[j] = fmaf(dv, xv[v + j], a[j]);
        }
    }
    float4 o = make_float4(a[0], a[1], a[2], a[3]);
    *(float4*)&out[(size_t)bc * HW + (y0 + row) * W_ + t4] = o;
}

// ---------------- launch ----------------
extern "C" void kernel_launch(void* const* d_in, const int* in_sizes, int n_in,
                              void* d_out, int out_size) {
    const float* x = (const float*)d_in[0];
    const float* w = (const float*)d_in[1];
    float* out = (float*)d_out;

    static bool attr_set = false;
    if (!attr_set) {
        cudaFuncSetAttribute(main_mma_kernel,
                             cudaFuncAttributeMaxDynamicSharedMemorySize, DSMEM);
        attr_set = true;
    }

    prep_kernel<<<400, 256>>>(w);
    main_mma_kernel<<<dim3(32, 16), 512, DSMEM>>>(x);
    dog_kernel<<<dim3(1024, 8), 512>>>(out);
}

// round 16
// speedup vs baseline: 1.2140x; 1.0853x over previous
#include <cuda_runtime.h>
#include <cuda_fp16.h>
#include <cstdint>
#include <math.h>

// Problem constants
#define B_   16
#define CIN  64
#define COUT 64
#define H_   128
#define W_   128
#define HW   (H_*W_)          // 16384
#define NPIX (B_*COUT*HW)     // 16,777,216

#define XPAD 72               // halves per px row (144 B): ldmatrix rows 16B-aligned
#define WPAD 72
#define XROW (132 * XPAD)     // halves per staged input row

// ---------------- device scratch (static, no allocation) ----------------
__device__ __align__(16) __half g_wh[25 * 64 * WPAD];   // [khw][cout][WPAD]
__device__ float g_dog[25];
__device__ __align__(16) __half g_ybuf[NPIX];           // fp16 cosine-sim intermediate

__device__ __forceinline__ int refl(int i) {
    if (i < 0) return -i;
    if (i > 127) return 254 - i;
    return i;
}

__device__ __forceinline__ uint32_t smem_u32(const void* p) {
    uint32_t a;
    asm("{ .reg .u64 t; cvta.to.shared.u64 t, %1; cvt.u32.u64 %0, t; }"
        : "=r"(a) : "l"(p));
    return a;
}

// ---------------- kernel 1: weight prep ----------------
// grid 400, block 256: 64-thread slice s = tid>>6 handles one (cout, tap).
__global__ __launch_bounds__(256)
void prep_kernel(const float* __restrict__ w) {
    __shared__ float sh[4][2];
    const int tid = threadIdx.x;
    const int s   = tid >> 6;             // slice 0..3
    const int ci  = tid & 63;
    const int job = blockIdx.x * 4 + s;   // 0..1599
    const int o   = job / 25;
    const int khw = job % 25;

    float v = w[o * 1600 + ci * 25 + khw];
    float ss = v * v;
    #pragma unroll
    for (int off = 16; off > 0; off >>= 1)
        ss += __shfl_down_sync(0xFFFFFFFFu, ss, off);
    if ((ci & 31) == 0) sh[s][ci >> 5] = ss;
    __syncthreads();
    float tot = sh[s][0] + sh[s][1];
    float inv = 1.f / fmaxf(sqrtf(tot), 1e-12f);
    g_wh[(size_t)(khw * 64 + o) * WPAD + ci] = __float2half(fabsf(v) * inv);

    if (blockIdx.x == 0 && tid < 25) {
        int u = tid / 5 - 2, vv = tid % 5 - 2;
        float d2 = (float)(u * u + vv * vv);
        const float two_pi = 6.2831853071795864769f;
        const float ae = 1.f / (two_pi * 1.44f);   // sigma_e = 1.2
        const float ai = 1.f / (two_pi * 1.96f);   // sigma_i = 1.4
        float val = ae * expf(-d2 / (2.f * 1.44f)) - ai * expf(-d2 / (2.f * 1.96f));
        g_dog[tid] = val / (ae - ai);
    }
}

// ---------------- kernel 2: fp16 HMMA implicit-GEMM conv + cosine (R6 config) ----------------
// Grid (32, 16): CTA = 4 output y-rows x 128 px x 64 cout. 512 thr = 16 warps.
// Warp w: yrow g = w>>2, px block (w&3)*32. Warp tile M32 x N64. X staged ONCE (8 rows).
// W tiles for next kh prefetched into registers during the tap loop.
// smem: Ws[5kw][64][WPAD] 46080 | Xs[8 rows][132 px][XPAD] 152064 | Crow[8*132] | Ssum[4*132]
#define WS_BYTES (5 * 64 * WPAD * 2)            // 46080
#define XS_BYTES (8 * 132 * XPAD * 2)           // 152064
#define CROW_FLOATS (8 * 132)
#define SSUM_FLOATS (4 * 132)
#define DSMEM (WS_BYTES + XS_BYTES + (CROW_FLOATS + SSUM_FLOATS) * 4)  // 204480

__global__ __launch_bounds__(512, 1)
void main_mma_kernel(const float* __restrict__ x) {
    extern __shared__ char dsm[];
    __half* Ws   = (__half*)dsm;
    __half* Xs   = (__half*)(dsm + WS_BYTES);
    float*  Crow = (float*)(dsm + WS_BYTES + XS_BYTES);
    float*  Ssum = Crow + CROW_FLOATS;

    const int tid  = threadIdx.x;
    const int warp = tid >> 5;
    const int lane = tid & 31;
    const int g    = warp >> 2;           // output yrow 0..3
    const int px0  = (warp & 3) * 32;     // pixel block
    const int b    = blockIdx.y;
    const int y0   = blockIdx.x * 4;

    // ---- stage X once: 8 input rows, transpose [ci][px] -> [px][ci] ----
    for (int task = warp; task < 128; task += 16) {
        int s = task >> 4, q = task & 15;
        int gy = refl(y0 + s - 2);
        const float* base = x + ((size_t)b * CIN + q * 4) * HW + (size_t)gy * W_;
        #pragma unroll
        for (int k = 0; k < 5; k++) {
            int c = lane + 32 * k;
            if (c < 132) {
                int gc = refl(c - 2);
                float v0 = base[0 * HW + gc];
                float v1 = base[1 * HW + gc];
                float v2 = base[2 * HW + gc];
                float v3 = base[3 * HW + gc];
                uint32_t p0, p1;
                asm("cvt.rn.f16x2.f32 %0, %1, %2;" : "=r"(p0) : "f"(v1), "f"(v0));
                asm("cvt.rn.f16x2.f32 %0, %1, %2;" : "=r"(p1) : "f"(v3), "f"(v2));
                *(uint2*)(Xs + (size_t)s * XROW + (size_t)c * XPAD + q * 4) =
                    make_uint2(p0, p1);
            }
        }
    }

    // ---- prefetch kh=0 W tiles into registers (latency overlaps Crow/Ssum) ----
    uint4 wreg[6];
    {
        const uint4* src = (const uint4*)g_wh;
        #pragma unroll
        for (int j = 0; j < 6; j++) {
            int i = tid + j * 512;
            if (i < 2880) wreg[j] = src[i];
        }
    }
    __syncthreads();

    // ---- per staged-row column sums of x^2 ----
    for (int t = tid; t < 1056; t += 512) {
        int s = t / 132, c = t - s * 132;
        const uint4* p = (const uint4*)(Xs + (size_t)s * XROW + (size_t)c * XPAD);
        float sacc = 0.f;
        #pragma unroll
        for (int i = 0; i < 8; i++) {
            uint4 u = p[i];
            const uint32_t uu[4] = {u.x, u.y, u.z, u.w};
            #pragma unroll
            for (int j = 0; j < 4; j++) {
                float2 f = __half22float2(*(const __half2*)&uu[j]);
                sacc = fmaf(f.x, f.x, fmaf(f.y, f.y, sacc));
            }
        }
        Crow[t] = sacc;
    }
    __syncthreads();

    // ---- 5-row window sums -> Ssum[out row][padded col] ----
    for (int t = tid; t < 528; t += 512) {
        int r = t / 132, c = t - r * 132;
        Ssum[t] = Crow[(r + 0) * 132 + c] + Crow[(r + 1) * 132 + c]
                + Crow[(r + 2) * 132 + c] + Crow[(r + 3) * 132 + c]
                + Crow[(r + 4) * 132 + c];
    }

    // ---- accumulators ----
    float acc[2][8][4];
    #pragma unroll
    for (int mt = 0; mt < 2; mt++)
        #pragma unroll
        for (int nt = 0; nt < 8; nt++)
            #pragma unroll
            for (int i = 0; i < 4; i++) acc[mt][nt][i] = 0.f;

    // ldmatrix lane mappings (verified R5/R6)
    const int m_off = ((lane >> 3) & 1) * 8 + (lane & 7);      // A rows
    const int k_off = (lane >> 4) * 8;                          // A k segment
    const int brow  = (lane & 7) + ((lane >> 4) << 3);          // B n row
    const int bk    = ((lane >> 3) & 1) * 8;                    // B k segment

    for (int kh = 0; kh < 5; kh++) {
        __syncthreads();   // previous kh's taps done reading Ws
        // ---- store prefetched W to smem ----
        {
            uint4* dst = (uint4*)Ws;
            #pragma unroll
            for (int j = 0; j < 6; j++) {
                int i = tid + j * 512;
                if (i < 2880) dst[i] = wreg[j];
            }
        }
        __syncthreads();
        // ---- prefetch next kh's W (LDG latency hidden under tap loop) ----
        if (kh < 4) {
            const uint4* src = (const uint4*)(g_wh + (size_t)(kh + 1) * 5 * 64 * WPAD);
            #pragma unroll
            for (int j = 0; j < 6; j++) {
                int i = tid + j * 512;
                if (i < 2880) wreg[j] = src[i];
            }
        }

        #pragma unroll
        for (int kw = 0; kw < 5; kw++) {
            const __half* Ab = Xs + (size_t)(g + kh) * XROW
                                  + (size_t)(px0 + kw) * XPAD;
            // A fragments for all 4 k-chunks
            uint32_t a[4][2][4];
            #pragma unroll
            for (int kt = 0; kt < 4; kt++)
                #pragma unroll
                for (int mt = 0; mt < 2; mt++) {
                    uint32_t ad = smem_u32(Ab + (size_t)(mt * 16 + m_off) * XPAD
                                              + kt * 16 + k_off);
                    asm volatile(
                        "ldmatrix.sync.aligned.m8n8.x4.shared.b16 {%0,%1,%2,%3}, [%4];"
                        : "=r"(a[kt][mt][0]), "=r"(a[kt][mt][1]),
                          "=r"(a[kt][mt][2]), "=r"(a[kt][mt][3])
                        : "r"(ad));
                }
            // B via ldmatrix.x4: regs = {b0,b1 of nt even; b0,b1 of nt odd}
            #pragma unroll
            for (int np = 0; np < 4; np++) {
                #pragma unroll
                for (int kt = 0; kt < 4; kt++) {
                    uint32_t bb[4];
                    uint32_t bd = smem_u32(Ws + (size_t)(kw * 64 + np * 16 + brow) * WPAD
                                              + kt * 16 + bk);
                    asm volatile(
                        "ldmatrix.sync.aligned.m8n8.x4.shared.b16 {%0,%1,%2,%3}, [%4];"
                        : "=r"(bb[0]), "=r"(bb[1]), "=r"(bb[2]), "=r"(bb[3])
                        : "r"(bd));
                    #pragma unroll
                    for (int mt = 0; mt < 2; mt++) {
                        asm volatile(
                            "mma.sync.aligned.m16n8k16.row.col.f32.f16.f16.f32 "
                            "{%0,%1,%2,%3}, {%4,%5,%6,%7}, {%8,%9}, {%0,%1,%2,%3};"
                            : "+f"(acc[mt][2 * np][0]), "+f"(acc[mt][2 * np][1]),
                              "+f"(acc[mt][2 * np][2]), "+f"(acc[mt][2 * np][3])
                            : "r"(a[kt][mt][0]), "r"(a[kt][mt][1]),
                              "r"(a[kt][mt][2]), "r"(a[kt][mt][3]),
                              "r"(bb[0]), "r"(bb[1]));
                        asm volatile(
                            "mma.sync.aligned.m16n8k16.row.col.f32.f16.f16.f32 "
                            "{%0,%1,%2,%3}, {%4,%5,%6,%7}, {%8,%9}, {%0,%1,%2,%3};"
                            : "+f"(acc[mt][2 * np + 1][0]), "+f"(acc[mt][2 * np + 1][1]),
                              "+f"(acc[mt][2 * np + 1][2]), "+f"(acc[mt][2 * np + 1][3])
                            : "r"(a[kt][mt][0]), "r"(a[kt][mt][1]),
                              "r"(a[kt][mt][2]), "r"(a[kt][mt][3]),
                              "r"(bb[2]), "r"(bb[3]));
                    }
                }
            }
        }
    }
    __syncthreads();   // all taps done; Xs region reusable for epilogue

    // ---- epilogue: cosine norm + smem transpose + coalesced fp16 store ----
    float inv[2][2];
    #pragma unroll
    for (int mt = 0; mt < 2; mt++)
        #pragma unroll
        for (int h = 0; h < 2; h++) {
            int p = px0 + mt * 16 + (lane >> 2) + h * 8;
            const float* sp = Ssum + g * 132 + p;
            float s = sp[0] + sp[1] + sp[2] + sp[3] + sp[4];
            inv[mt][h] = rsqrtf(s + 1e-8f);
        }

    float* buf = (float*)(dsm + WS_BYTES) + warp * (64 * 36);
    #pragma unroll
    for (int mt = 0; mt < 2; mt++)
        #pragma unroll
        for (int nt = 0; nt < 8; nt++)
            #pragma unroll
            for (int reg = 0; reg < 4; reg++) {
                int co  = nt * 8 + (lane & 3) * 2 + (reg & 1);
                int pxl = mt * 16 + (lane >> 2) + (reg >> 1) * 8;
                buf[co * 36 + pxl] = acc[mt][nt][reg] * inv[mt][reg >> 1];
            }
    __syncwarp();

    const int y = y0 + g;
    #pragma unroll
    for (int it = 0; it < 16; it++) {
        int row = it * 4 + (lane >> 3);   // cout
        int seg = lane & 7;               // 4-px segment
        float4 v = *(const float4*)&buf[row * 36 + seg * 4];
        uint32_t h01, h23;
        asm("cvt.rn.f16x2.f32 %0, %1, %2;" : "=r"(h01) : "f"(v.y), "f"(v.x));
        asm("cvt.rn.f16x2.f32 %0, %1, %2;" : "=r"(h23) : "f"(v.w), "f"(v.z));
        *(uint2*)&g_ybuf[(((size_t)b * COUT + row) * H_ + y) * W_ + px0 + seg * 4] =
            make_uint2(h01, h23);
    }
}

// ---------------- kernel 3: depthwise 5x5 DoG (zero pad), fp16 input, 32-row tiles ----------------
__global__ __launch_bounds__(512)
void dog_kernel(float* __restrict__ out) {
    __shared__ float Ts[36 * 132];
    __shared__ float sd[25];

    const int tid = threadIdx.x;
    const int bc  = blockIdx.x;
    const int y0  = blockIdx.y * 32;

    if (tid < 25) sd[tid] = g_dog[tid];

    const __half* src = g_ybuf + (size_t)bc * HW;
    for (int idx = tid; idx < 36 * 66; idx += 512) {
        int rr = idx / 66;
        int c2 = (idx - rr * 66) * 2;         // padded col pair base
        int gy = y0 + rr - 2;
        float2 f = make_float2(0.f, 0.f);
        if (gy >= 0 && gy < H_) {
            int gx = c2 - 2;
            if (gx >= 0 && gx + 1 < W_) {
                f = __half22float2(*(const __half2*)(src + gy * W_ + gx));
            } else {
                if (gx >= 0 && gx < W_)         f.x = __half2float(src[gy * W_ + gx]);
                if (gx + 1 >= 0 && gx + 1 < W_) f.y = __half2float(src[gy * W_ + gx + 1]);
            }
        }
        Ts[rr * 132 + c2]     = f.x;
        Ts[rr * 132 + c2 + 1] = f.y;
    }
    __syncthreads();

    const int t4 = (tid & 31) * 4;
    #pragma unroll
    for (int it = 0; it < 2; it++) {
        const int row = (tid >> 5) + it * 16;   // 0..31
        float a[4] = {0.f, 0.f, 0.f, 0.f};
        #pragma unroll
        for (int u = 0; u < 5; u++) {
            const float* rp = &Ts[(row + u) * 132 + t4];
            float4 xa = *(const float4*)rp;
            float4 xc = *(const float4*)(rp + 4);
            float xv[8] = {xa.x, xa.y, xa.z, xa.w, xc.x, xc.y, xc.z, xc.w};
            #pragma unroll
            for (int v = 0; v < 5; v++) {
                float dv = sd[u * 5 + v];
                #pragma unroll
                for (int j = 0; j < 4; j++) a[j] = fmaf(dv, xv[v + j], a[j]);
            }
        }
        float4 o = make_float4(a[0], a[1], a[2], a[3]);
        *(float4*)&out[(size_t)bc * HW + (y0 + row) * W_ + t4] = o;
    }
}

// ---------------- launch ----------------
extern "C" void kernel_launch(void* const* d_in, const int* in_sizes, int n_in,
                              void* d_out, int out_size) {
    const float* x = (const float*)d_in[0];
    const float* w = (const float*)d_in[1];
    float* out = (float*)d_out;

    static bool attr_set = false;
    if (!attr_set) {
        cudaFuncSetAttribute(main_mma_kernel,
                             cudaFuncAttributeMaxDynamicSharedMemorySize, DSMEM);
        attr_set = true;
    }

    prep_kernel<<<400, 256>>>(w);
    main_mma_kernel<<<dim3(32, 16), 512, DSMEM>>>(x);
    dog_kernel<<<dim3(1024, 4), 512>>>(out);
}

// round 17
// speedup vs baseline: 1.2152x; 1.0010x over previous
#include <cuda_runtime.h>
#include <cuda_fp16.h>
#include <cstdint>
#include <math.h>

// Problem constants
#define B_   16
#define CIN  64
#define COUT 64
#define H_   128
#define W_   128
#define HW   (H_*W_)          // 16384
#define NPIX (B_*COUT*HW)     // 16,777,216

#define XPAD 72               // halves per px row (144 B): ldmatrix rows 16B-aligned
#define WPAD 72
#define XROW (132 * XPAD)     // halves per staged input row

// ---------------- device scratch (static, no allocation) ----------------
__device__ __align__(16) __half g_wh[25 * 64 * WPAD];   // [khw][cout][WPAD]
__device__ float g_dog[25];
__device__ __align__(16) __half g_ybuf[NPIX];           // fp16 cosine-sim intermediate

__device__ __forceinline__ int refl(int i) {
    if (i < 0) return -i;
    if (i > 127) return 254 - i;
    return i;
}

__device__ __forceinline__ uint32_t smem_u32(const void* p) {
    uint32_t a;
    asm("{ .reg .u64 t; cvta.to.shared.u64 t, %1; cvt.u32.u64 %0, t; }"
        : "=r"(a) : "l"(p));
    return a;
}

// ---------------- kernel 1: weight prep ----------------
__global__ __launch_bounds__(256)
void prep_kernel(const float* __restrict__ w) {
    __shared__ float sh[4][2];
    const int tid = threadIdx.x;
    const int s   = tid >> 6;             // slice 0..3
    const int ci  = tid & 63;
    const int job = blockIdx.x * 4 + s;   // 0..1599
    const int o   = job / 25;
    const int khw = job % 25;

    float v = w[o * 1600 + ci * 25 + khw];
    float ss = v * v;
    #pragma unroll
    for (int off = 16; off > 0; off >>= 1)
        ss += __shfl_down_sync(0xFFFFFFFFu, ss, off);
    if ((ci & 31) == 0) sh[s][ci >> 5] = ss;
    __syncthreads();
    float tot = sh[s][0] + sh[s][1];
    float inv = 1.f / fmaxf(sqrtf(tot), 1e-12f);
    g_wh[(size_t)(khw * 64 + o) * WPAD + ci] = __float2half(fabsf(v) * inv);

    if (blockIdx.x == 0 && tid < 25) {
        int u = tid / 5 - 2, vv = tid % 5 - 2;
        float d2 = (float)(u * u + vv * vv);
        const float two_pi = 6.2831853071795864769f;
        const float ae = 1.f / (two_pi * 1.44f);   // sigma_e = 1.2
        const float ai = 1.f / (two_pi * 1.96f);   // sigma_i = 1.4
        float val = ae * expf(-d2 / (2.f * 1.44f)) - ai * expf(-d2 / (2.f * 1.96f));
        g_dog[tid] = val / (ae - ai);
    }
}

// ---------------- kernel 2: fp16 HMMA conv + cosine, K-split warp pairs ----------------
// Grid (64, 16): CTA = 2 output y-rows x 128 px x 64 cout. 512 thr = 16 warps.
// Tile t = warp&7: g = t>>2 (yrow), px0 = (t&3)*32. kslice = warp>>3 covers ci
// [kslice*32, kslice*32+32) over ALL 25 taps (homogeneous). Epilogue smem-reduce.
// smem: Ws[5kw][64][WPAD] 46080 | Xs[6 rows][132][XPAD] 114048 | Crow[6*132] | Ssum[2*132]
#define WS_BYTES (5 * 64 * WPAD * 2)            // 46080
#define XS_BYTES (6 * 132 * XPAD * 2)           // 114048
#define CROW_FLOATS (6 * 132)
#define SSUM_FLOATS (2 * 132)
#define DSMEM (WS_BYTES + XS_BYTES + (CROW_FLOATS + SSUM_FLOATS) * 4)  // 164352
// epilogue reuse of dead Ws/Xs region (Ssum at tail offset 163296 stays live):
#define DUMP_OFF 0          // 8 tiles x 2048 floats = 65536 B
#define TBUF_OFF 65536      // 8 A-warps x 64*36 floats = 73728 B (ends 139264 < 160128)

__global__ __launch_bounds__(512, 1)
void main_mma_kernel(const float* __restrict__ x) {
    extern __shared__ char dsm[];
    __half* Ws   = (__half*)dsm;
    __half* Xs   = (__half*)(dsm + WS_BYTES);
    float*  Crow = (float*)(dsm + WS_BYTES + XS_BYTES);
    float*  Ssum = Crow + CROW_FLOATS;

    const int tid  = threadIdx.x;
    const int warp = tid >> 5;
    const int lane = tid & 31;
    const int t    = warp & 7;            // tile 0..7
    const int g    = t >> 2;              // output yrow 0..1
    const int px0  = (t & 3) * 32;        // pixel block
    const int ks   = (warp >> 3) * 32;    // ci slice offset 0 / 32
    const int b    = blockIdx.y;
    const int y0   = blockIdx.x * 2;

    // ---- stage X once: 6 input rows, transpose [ci][px] -> [px][ci] ----
    for (int task = warp; task < 96; task += 16) {
        int s = task >> 4, q = task & 15;
        int gy = refl(y0 + s - 2);
        const float* base = x + ((size_t)b * CIN + q * 4) * HW + (size_t)gy * W_;
        #pragma unroll
        for (int k = 0; k < 5; k++) {
            int c = lane + 32 * k;
            if (c < 132) {
                int gc = refl(c - 2);
                float v0 = base[0 * HW + gc];
                float v1 = base[1 * HW + gc];
                float v2 = base[2 * HW + gc];
                float v3 = base[3 * HW + gc];
                uint32_t p0, p1;
                asm("cvt.rn.f16x2.f32 %0, %1, %2;" : "=r"(p0) : "f"(v1), "f"(v0));
                asm("cvt.rn.f16x2.f32 %0, %1, %2;" : "=r"(p1) : "f"(v3), "f"(v2));
                *(uint2*)(Xs + (size_t)s * XROW + (size_t)c * XPAD + q * 4) =
                    make_uint2(p0, p1);
            }
        }
    }

    // ---- prefetch kh=0 W tiles into registers ----
    uint4 wreg[6];
    {
        const uint4* src = (const uint4*)g_wh;
        #pragma unroll
        for (int j = 0; j < 6; j++) {
            int i = tid + j * 512;
            if (i < 2880) wreg[j] = src[i];
        }
    }
    __syncthreads();

    // ---- per staged-row column sums of x^2 ----
    for (int tt = tid; tt < 792; tt += 512) {
        int s = tt / 132, c = tt - s * 132;
        const uint4* p = (const uint4*)(Xs + (size_t)s * XROW + (size_t)c * XPAD);
        float sacc = 0.f;
        #pragma unroll
        for (int i = 0; i < 8; i++) {
            uint4 u = p[i];
            const uint32_t uu[4] = {u.x, u.y, u.z, u.w};
            #pragma unroll
            for (int j = 0; j < 4; j++) {
                float2 f = __half22float2(*(const __half2*)&uu[j]);
                sacc = fmaf(f.x, f.x, fmaf(f.y, f.y, sacc));
            }
        }
        Crow[tt] = sacc;
    }
    __syncthreads();

    // ---- 5-row window sums -> Ssum[out row][padded col] ----
    for (int tt = tid; tt < 264; tt += 512) {
        int r = tt / 132, c = tt - r * 132;
        Ssum[tt] = Crow[(r + 0) * 132 + c] + Crow[(r + 1) * 132 + c]
                 + Crow[(r + 2) * 132 + c] + Crow[(r + 3) * 132 + c]
                 + Crow[(r + 4) * 132 + c];
    }

    // ---- accumulators ----
    float acc[2][8][4];
    #pragma unroll
    for (int mt = 0; mt < 2; mt++)
        #pragma unroll
        for (int nt = 0; nt < 8; nt++)
            #pragma unroll
            for (int i = 0; i < 4; i++) acc[mt][nt][i] = 0.f;

    // ldmatrix lane mappings (verified R5/R6)
    const int m_off = ((lane >> 3) & 1) * 8 + (lane & 7);      // A rows
    const int k_off = (lane >> 4) * 8;                          // A k segment
    const int brow  = (lane & 7) + ((lane >> 4) << 3);          // B n row
    const int bk    = ((lane >> 3) & 1) * 8;                    // B k segment

    for (int kh = 0; kh < 5; kh++) {
        __syncthreads();   // previous kh's taps done reading Ws
        {
            uint4* dst = (uint4*)Ws;
            #pragma unroll
            for (int j = 0; j < 6; j++) {
                int i = tid + j * 512;
                if (i < 2880) dst[i] = wreg[j];
            }
        }
        __syncthreads();
        if (kh < 4) {      // prefetch next kh's W; latency hidden under taps
            const uint4* src = (const uint4*)(g_wh + (size_t)(kh + 1) * 5 * 64 * WPAD);
            #pragma unroll
            for (int j = 0; j < 6; j++) {
                int i = tid + j * 512;
                if (i < 2880) wreg[j] = src[i];
            }
        }

        #pragma unroll
        for (int kw = 0; kw < 5; kw++) {
            const __half* Ab = Xs + (size_t)(g + kh) * XROW
                                  + (size_t)(px0 + kw) * XPAD + ks;
            // A fragments: 2 k-chunks (this warp's 32 ci)
            uint32_t a[2][2][4];
            #pragma unroll
            for (int kt = 0; kt < 2; kt++)
                #pragma unroll
                for (int mt = 0; mt < 2; mt++) {
                    uint32_t ad = smem_u32(Ab + (size_t)(mt * 16 + m_off) * XPAD
                                              + kt * 16 + k_off);
                    asm volatile(
                        "ldmatrix.sync.aligned.m8n8.x4.shared.b16 {%0,%1,%2,%3}, [%4];"
                        : "=r"(a[kt][mt][0]), "=r"(a[kt][mt][1]),
                          "=r"(a[kt][mt][2]), "=r"(a[kt][mt][3])
                        : "r"(ad));
                }
            #pragma unroll
            for (int np = 0; np < 4; np++) {
                #pragma unroll
                for (int kt = 0; kt < 2; kt++) {
                    uint32_t bb[4];
                    uint32_t bd = smem_u32(Ws + (size_t)(kw * 64 + np * 16 + brow) * WPAD
                                              + ks + kt * 16 + bk);
                    asm volatile(
                        "ldmatrix.sync.aligned.m8n8.x4.shared.b16 {%0,%1,%2,%3}, [%4];"
                        : "=r"(bb[0]), "=r"(bb[1]), "=r"(bb[2]), "=r"(bb[3])
                        : "r"(bd));
                    #pragma unroll
                    for (int mt = 0; mt < 2; mt++) {
                        asm volatile(
                            "mma.sync.aligned.m16n8k16.row.col.f32.f16.f16.f32 "
                            "{%0,%1,%2,%3}, {%4,%5,%6,%7}, {%8,%9}, {%0,%1,%2,%3};"
                            : "+f"(acc[mt][2 * np][0]), "+f"(acc[mt][2 * np][1]),
                              "+f"(acc[mt][2 * np][2]), "+f"(acc[mt][2 * np][3])
                            : "r"(a[kt][mt][0]), "r"(a[kt][mt][1]),
                              "r"(a[kt][mt][2]), "r"(a[kt][mt][3]),
                              "r"(bb[0]), "r"(bb[1]));
                        asm volatile(
                            "mma.sync.aligned.m16n8k16.row.col.f32.f16.f16.f32 "
                            "{%0,%1,%2,%3}, {%4,%5,%6,%7}, {%8,%9}, {%0,%1,%2,%3};"
                            : "+f"(acc[mt][2 * np + 1][0]), "+f"(acc[mt][2 * np + 1][1]),
                              "+f"(acc[mt][2 * np + 1][2]), "+f"(acc[mt][2 * np + 1][3])
                            : "r"(a[kt][mt][0]), "r"(a[kt][mt][1]),
                              "r"(a[kt][mt][2]), "r"(a[kt][mt][3]),
                              "r"(bb[2]), "r"(bb[3]));
                    }
                }
            }
        }
    }
    __syncthreads();   // all taps done; Ws/Xs dead (Ssum at tail stays live)

    // ---- K-slice 1 warps dump raw accumulators (numerators add before division) ----
    float* dump = (float*)(dsm + DUMP_OFF) + t * 2048;
    if (ks) {
        int idx = 0;
        #pragma unroll
        for (int mt = 0; mt < 2; mt++)
            #pragma unroll
            for (int nt = 0; nt < 8; nt++)
                #pragma unroll
                for (int reg = 0; reg < 4; reg++)
                    dump[(idx++) * 32 + lane] = acc[mt][nt][reg];
    }
    __syncthreads();

    if (!ks) {
        {
            int idx = 0;
            #pragma unroll
            for (int mt = 0; mt < 2; mt++)
                #pragma unroll
                for (int nt = 0; nt < 8; nt++)
                    #pragma unroll
                    for (int reg = 0; reg < 4; reg++)
                        acc[mt][nt][reg] += dump[(idx++) * 32 + lane];
        }

        // ---- cosine norm + smem transpose + coalesced fp16 store ----
        float inv[2][2];
        #pragma unroll
        for (int mt = 0; mt < 2; mt++)
            #pragma unroll
            for (int h = 0; h < 2; h++) {
                int p = px0 + mt * 16 + (lane >> 2) + h * 8;
                const float* sp = Ssum + g * 132 + p;
                float s = sp[0] + sp[1] + sp[2] + sp[3] + sp[4];
                inv[mt][h] = rsqrtf(s + 1e-8f);
            }

        float* buf = (float*)(dsm + TBUF_OFF) + warp * (64 * 36);
        #pragma unroll
        for (int mt = 0; mt < 2; mt++)
            #pragma unroll
            for (int nt = 0; nt < 8; nt++)
                #pragma unroll
                for (int reg = 0; reg < 4; reg++) {
                    int co  = nt * 8 + (lane & 3) * 2 + (reg & 1);
                    int pxl = mt * 16 + (lane >> 2) + (reg >> 1) * 8;
                    buf[co * 36 + pxl] = acc[mt][nt][reg] * inv[mt][reg >> 1];
                }
        __syncwarp();

        const int y = y0 + g;
        #pragma unroll
        for (int it = 0; it < 16; it++) {
            int row = it * 4 + (lane >> 3);   // cout
            int seg = lane & 7;               // 4-px segment
            float4 v = *(const float4*)&buf[row * 36 + seg * 4];
            uint32_t h01, h23;
            asm("cvt.rn.f16x2.f32 %0, %1, %2;" : "=r"(h01) : "f"(v.y), "f"(v.x));
            asm("cvt.rn.f16x2.f32 %0, %1, %2;" : "=r"(h23) : "f"(v.w), "f"(v.z));
            *(uint2*)&g_ybuf[(((size_t)b * COUT + row) * H_ + y) * W_ + px0 + seg * 4] =
                make_uint2(h01, h23);
        }
    }
}

// ---------------- kernel 3: depthwise 5x5 DoG (zero pad), fp16 input, 32-row tiles ----------------
__global__ __launch_bounds__(512)
void dog_kernel(float* __restrict__ out) {
    __shared__ float Ts[36 * 132];
    __shared__ float sd[25];

    const int tid = threadIdx.x;
    const int bc  = blockIdx.x;
    const int y0  = blockIdx.y * 32;

    if (tid < 25) sd[tid] = g_dog[tid];

    const __half* src = g_ybuf + (size_t)bc * HW;
    for (int idx = tid; idx < 36 * 66; idx += 512) {
        int rr = idx / 66;
        int c2 = (idx - rr * 66) * 2;
        int gy = y0 + rr - 2;
        float2 f = make_float2(0.f, 0.f);
        if (gy >= 0 && gy < H_) {
            int gx = c2 - 2;
            if (gx >= 0 && gx + 1 < W_) {
                f = __half22float2(*(const __half2*)(src + gy * W_ + gx));
            } else {
                if (gx >= 0 && gx < W_)         f.x = __half2float(src[gy * W_ + gx]);
                if (gx + 1 >= 0 && gx + 1 < W_) f.y = __half2float(src[gy * W_ + gx + 1]);
            }
        }
        Ts[rr * 132 + c2]     = f.x;
        Ts[rr * 132 + c2 + 1] = f.y;
    }
    __syncthreads();

    const int t4 = (tid & 31) * 4;
    #pragma unroll
    for (int it = 0; it < 2; it++) {
        const int row = (tid >> 5) + it * 16;   // 0..31
        float a[4] = {0.f, 0.f, 0.f, 0.f};
        #pragma unroll
        for (int u = 0; u < 5; u++) {
            const float* rp = &Ts[(row + u) * 132 + t4];
            float4 xa = *(const float4*)rp;
            float4 xc = *(const float4*)(rp + 4);
            float xv[8] = {xa.x, xa.y, xa.z, xa.w, xc.x, xc.y, xc.z, xc.w};
            #pragma unroll
            for (int v = 0; v < 5; v++) {
                float dv = sd[u * 5 + v];
                #pragma unroll
                for (int j = 0; j < 4; j++) a[j] = fmaf(dv, xv[v + j], a[j]);
            }
        }
        float4 o = make_float4(a[0], a[1], a[2], a[3]);
        *(float4*)&out[(size_t)bc * HW + (y0 + row) * W_ + t4] = o;
    }
}

// ---------------- launch ----------------
extern "C" void kernel_launch(void* const* d_in, const int* in_sizes, int n_in,
                              void* d_out, int out_size) {
    const float* x = (const float*)d_in[0];
    const float* w = (const float*)d_in[1];
    float* out = (float*)d_out;

    static bool attr_set = false;
    if (!attr_set) {
        cudaFuncSetAttribute(main_mma_kernel,
                             cudaFuncAttributeMaxDynamicSharedMemorySize, DSMEM);
        attr_set = true;
    }

    prep_kernel<<<400, 256>>>(w);
    main_mma_kernel<<<dim3(64, 16), 512, DSMEM>>>(x);
    dog_kernel<<<dim3(1024, 4), 512>>>(out);
}